// round 8
// baseline (speedup 1.0000x reference)
#include <cuda_runtime.h>
#include <cstdint>

// 64 steps of diffusion-advection on a 1024x1024 periodic grid, emitting
// (T, 3, H, W) fp32 RGB, as ONE persistent kernel.
//
//  - State u ping-pongs in two dedicated 4 MB __device__ buffers that stay
//    L2-resident (re-touched every 2 steps). The sync-critical chain touches
//    ONLY these: spin -> halo LDG (L2 hit) -> compute -> state store (L2)
//    -> bar -> release flag.
//  - All frame output (r,g,b = 12.6 MB/step, never read) is issued AFTER the
//    flag publish with streaming stores, draining in the shadow of the next
//    step's spin + compute.
//  - Per-row flags, ld.acquire.gpu spin / st.release.gpu publish; one
//    __syncthreads per step. Warp-edge x-neighbors via parity smem slots.

#define HH 1024
#define WW 1024
#define HW (HH * WW)

#define DT     0.1f
#define ALPHA  0.05f
#define V_X    0.1f
// V_Y == 0 -> du_dy term vanishes.

#define NB 1024
#define FS 32                 // flag stride in ints (128 B)

__device__ int   g_flags[NB * FS];
__device__ float g_state[2][HW];      // ping-pong u buffers (L2-resident)

__global__ void reset_flags_kernel() {
    const int i = blockIdx.x * blockDim.x + threadIdx.x;   // 0..NB-1
    g_flags[i * FS] = 0;
}

__device__ __forceinline__ int ld_acq(const int* p) {
    int v;
    asm volatile("ld.acquire.gpu.global.b32 %0, [%1];"
                 : "=r"(v) : "l"(p) : "memory");
    return v;
}
__device__ __forceinline__ void st_rel(int* p, int v) {
    asm volatile("st.release.gpu.global.b32 [%0], %1;"
                 :: "l"(p), "r"(v) : "memory");
}

__global__ __launch_bounds__(256, 8)
void physics_persistent_kernel(const float* __restrict__ u_init,
                               float* __restrict__ frames,
                               int n_frames)
{
    // Edge exchange: [parity][0=first elem of warp][wid], [1=last][wid]
    __shared__ float sEdge[2][2][8];

    const int y    = blockIdx.x;          // owned row
    const int c4   = threadIdx.x;         // float4 column 0..255
    const int lane = c4 & 31;
    const int wid  = c4 >> 5;
    const int ym1  = (y - 1) & (HH - 1);
    const int yp1  = (y + 1) & (HH - 1);

    const int idx  = (y   << 8) + c4;     // float4 index within a channel
    const int idxu = (ym1 << 8) + c4;
    const int idxd = (yp1 << 8) + c4;

    int*       flag_self = &g_flags[y   * FS];
    const int* flag_up   = &g_flags[ym1 * FS];
    const int* flag_dn   = &g_flags[yp1 * FS];

    float4 u = ((const float4*)u_init)[idx];   // u_s for own row
    float* fr = frames;                        // frame s base

    if (lane == 0)  sEdge[0][0][wid] = u.x;
    if (lane == 31) sEdge[0][1][wid] = u.w;
    __syncthreads();

    for (int s = 0; s < n_frames; ++s) {
        // u_s lives in: u_init (s==0) or g_state[s&1].
        const float4* src4 = (s == 0) ? (const float4*)u_init
                                      : (const float4*)g_state[s & 1];

        if (s > 0) {
            while (ld_acq(flag_up) < s) { }
            while (ld_acq(flag_dn) < s) { }
        }

        const float4 hu = __ldcg(&src4[idxu]);
        const float4 hd = __ldcg(&src4[idxd]);

        const int par = s & 1;
        const float lwS = sEdge[par][1][(wid - 1) & 7];
        const float rxS = sEdge[par][0][(wid + 1) & 7];

        float lw = __shfl_up_sync(0xffffffffu, u.w, 1);
        float rx = __shfl_down_sync(0xffffffffu, u.x, 1);
        if (lane == 0)  lw = lwS;
        if (lane == 31) rx = rxS;

        const float uc[4] = {u.x,  u.y,  u.z,  u.w};
        const float ul[4] = {lw,   u.x,  u.y,  u.z};
        const float ur[4] = {u.y,  u.z,  u.w,  rx};
        const float uu[4] = {hu.x, hu.y, hu.z, hu.w};
        const float ud[4] = {hd.x, hd.y, hd.z, hd.w};

        float4 n;
        float* np = &n.x;
        #pragma unroll
        for (int i = 0; i < 4; ++i) {
            const float lap = ul[i] + ur[i] + uu[i] + ud[i] - 4.0f * uc[i];
            float v = uc[i] + DT * (ALPHA * lap - V_X * (uc[i] - ul[i]));
            np[i] = fminf(fmaxf(v, 0.0f), 1.0f);
        }

        // State store (L2-hot small buffer) -- the only store on the chain.
        ((float4*)g_state[(s + 1) & 1])[idx] = n;

        // Stage next step's warp edges (other parity slot).
        if (lane == 0)  sEdge[par ^ 1][0][wid] = n.x;
        if (lane == 31) sEdge[par ^ 1][1][wid] = n.w;

        // Publish: barrier orders state store + edge STS, then release.
        __syncthreads();
        if (c4 == 0) st_rel(flag_self, s + 1);

        // Frame output (never read by anyone): streaming, off the chain.
        float4* f4 = (float4*)fr;
        __stcs(&f4[idx], n);                       // r
        float4 t;
        t.x = n.x * 0.5f; t.y = n.y * 0.5f;
        t.z = n.z * 0.5f; t.w = n.w * 0.5f;
        __stcs(&f4[idx + (HW / 4)], t);            // g
        t.x = 1.0f - n.x; t.y = 1.0f - n.y;
        t.z = 1.0f - n.z; t.w = 1.0f - n.w;
        __stcs(&f4[idx + 2 * (HW / 4)], t);        // b

        u  = n;
        fr += 3 * HW;
    }
}

extern "C" void kernel_launch(void* const* d_in, const int* in_sizes, int n_in,
                              void* d_out, int out_size) {
    const float* init = (const float*)d_in[0];
    float* out = (float*)d_out;
    const int n_frames = out_size / (3 * HW);

    reset_flags_kernel<<<NB / 256, 256>>>();
    physics_persistent_kernel<<<NB, 256>>>(init, out, n_frames);
}

// round 9
// speedup vs baseline: 1.1664x; 1.1664x over previous
#include <cuda_runtime.h>
#include <cstdint>

// 64 steps of diffusion-advection on a 1024x1024 periodic grid -> (T,3,H,W)
// fp32 RGB, ONE persistent kernel, TWO time steps fused per sync round.
//
//  - r channel of frame s == u_{s+1} exactly (clipped); frames carry state.
//  - Block owns rows {2b, 2b+1} in registers. Per iteration k: consume
//    u_{2k}, produce frames 2k (intermediate) and 2k+1 (final). Only the
//    final r store precedes the flag; everything else streams after it.
//  - Intermediate x-neighbors: register shuffles + smem warp-edge exchange
//    across one __syncthreads (block spans the full 1024-wide row; x wraps
//    inside the block).
//  - 512 blocks x 256 threads, <=64 regs -> 4 blocks/SM, 592 slots >= 512:
//    full co-residency (spin-safe).

#define HH 1024
#define WW 1024
#define HW (HH * WW)

#define DT     0.1f
#define ALPHA  0.05f
#define V_X    0.1f
// V_Y == 0 -> du_dy term vanishes.

#define NB 512
#define FS 32                 // flag stride in ints (128 B)

__device__ int g_flags[NB * FS];

__global__ void reset_flags_kernel() {
    const int i = blockIdx.x * blockDim.x + threadIdx.x;   // 0..NB-1
    g_flags[i * FS] = 0;
}

__device__ __forceinline__ int ld_acq(const int* p) {
    int v;
    asm volatile("ld.acquire.gpu.global.b32 %0, [%1];"
                 : "=r"(v) : "l"(p) : "memory");
    return v;
}
__device__ __forceinline__ void st_rel(int* p, int v) {
    asm volatile("st.release.gpu.global.b32 [%0], %1;"
                 :: "l"(p), "r"(v) : "memory");
}

// One stencil step for one row (4 lanes wide).
__device__ __forceinline__ float4 step_row(const float4 up, const float4 ce,
                                           const float4 dn,
                                           const float lw, const float rx) {
    const float uc[4] = {ce.x, ce.y, ce.z, ce.w};
    const float ul[4] = {lw,   ce.x, ce.y, ce.z};
    const float ur[4] = {ce.y, ce.z, ce.w, rx};
    const float uu[4] = {up.x, up.y, up.z, up.w};
    const float ud[4] = {dn.x, dn.y, dn.z, dn.w};
    float4 n;
    float* np = &n.x;
    #pragma unroll
    for (int i = 0; i < 4; ++i) {
        const float lap = ul[i] + ur[i] + uu[i] + ud[i] - 4.0f * uc[i];
        float v = uc[i] + DT * (ALPHA * lap - V_X * (uc[i] - ul[i]));
        np[i] = fminf(fmaxf(v, 0.0f), 1.0f);
    }
    return n;
}

__device__ __forceinline__ void emit_gb(float4* f4, int idx, const float4 n) {
    float4 t;
    t.x = n.x * 0.5f; t.y = n.y * 0.5f;
    t.z = n.z * 0.5f; t.w = n.w * 0.5f;
    __stcs(&f4[idx + (HW / 4)], t);
    t.x = 1.0f - n.x; t.y = 1.0f - n.y;
    t.z = 1.0f - n.z; t.w = 1.0f - n.w;
    __stcs(&f4[idx + 2 * (HW / 4)], t);
}

__global__ __launch_bounds__(256, 4)
void physics_persistent_kernel(const float* __restrict__ u_init,
                               float* __restrict__ frames,
                               int n_frames)
{
    __shared__ float eX[8][4];   // lane0's  M[m].x per warp
    __shared__ float eW[8][4];   // lane31's M[m].w per warp

    const int b    = blockIdx.x;
    const int c4   = threadIdx.x;
    const int lane = c4 & 31;
    const int wid  = c4 >> 5;
    const int y0   = 2 * b;
    const int x0   = c4 << 2;
    const int xm1  = (x0 - 1) & (WW - 1);
    const int xp4  = (x0 + 4) & (WW - 1);

    // Source rows y0-2 .. y0+3 (periodic)
    int gy[6], idx4[6], eL[6], eR[6];
    #pragma unroll
    for (int i = 0; i < 6; ++i) {
        gy[i]   = (y0 - 2 + i) & (HH - 1);
        idx4[i] = (gy[i] << 8) + c4;
        eL[i]   = (gy[i] << 10) + xm1;
        eR[i]   = (gy[i] << 10) + xp4;
    }
    const int i0 = idx4[2];   // row y0
    const int i1 = idx4[3];   // row y0+1

    int*       flag_self = &g_flags[b * FS];
    const int* flag_up   = &g_flags[((b - 1) & (NB - 1)) * FS];
    const int* flag_dn   = &g_flags[((b + 1) & (NB - 1)) * FS];

    const float4* init4 = (const float4*)u_init;
    float4 u0 = init4[i0];
    float4 u1 = init4[i1];

    const float* src = u_init;     // where u_{2k} lives
    float*       fr  = frames;     // frame 2k base

    const int n_iter = n_frames >> 1;   // n_frames is even (64)

    for (int k = 0; k < n_iter; ++k) {
        if (k > 0) {
            while (ld_acq(flag_up) < k) { }
            while (ld_acq(flag_dn) < k) { }
        }

        const float4* src4 = (const float4*)src;
        float4 S0 = __ldcg(&src4[idx4[0]]);
        float4 S1 = __ldcg(&src4[idx4[1]]);
        float4 S4 = __ldcg(&src4[idx4[4]]);
        float4 S5 = __ldcg(&src4[idx4[5]]);
        const float4 S[6] = {S0, S1, u0, u1, S4, S5};

        // x-neighbors of all 6 source rows
        float lw[6], rx[6];
        #pragma unroll
        for (int i = 0; i < 6; ++i) {
            lw[i] = __shfl_up_sync(0xffffffffu, S[i].w, 1);
            rx[i] = __shfl_down_sync(0xffffffffu, S[i].x, 1);
        }
        if (lane == 0) {
            #pragma unroll
            for (int i = 0; i < 6; ++i) lw[i] = __ldcg(&src[eL[i]]);
        }
        if (lane == 31) {
            #pragma unroll
            for (int i = 0; i < 6; ++i) rx[i] = __ldcg(&src[eR[i]]);
        }

        // Step 1: intermediates u_{2k+1} for rows y0-1 .. y0+2
        float4 M[4];
        #pragma unroll
        for (int m = 0; m < 4; ++m)
            M[m] = step_row(S[m], S[m + 1], S[m + 2], lw[m + 1], rx[m + 1]);

        // Warp-edge exchange of intermediates
        if (lane == 0) {
            #pragma unroll
            for (int m = 0; m < 4; ++m) eX[wid][m] = M[m].x;
        }
        if (lane == 31) {
            #pragma unroll
            for (int m = 0; m < 4; ++m) eW[wid][m] = M[m].w;
        }
        __syncthreads();

        float lwI[4], rxI[4];
        #pragma unroll
        for (int m = 0; m < 4; ++m) {
            lwI[m] = __shfl_up_sync(0xffffffffu, M[m].w, 1);
            rxI[m] = __shfl_down_sync(0xffffffffu, M[m].x, 1);
        }
        if (lane == 0) {
            #pragma unroll
            for (int m = 0; m < 4; ++m) lwI[m] = eW[(wid + 7) & 7][m];
        }
        if (lane == 31) {
            #pragma unroll
            for (int m = 0; m < 4; ++m) rxI[m] = eX[(wid + 1) & 7][m];
        }

        // Step 2: finals u_{2k+2} for own rows
        const float4 F0 = step_row(M[0], M[1], M[2], lwI[1], rxI[1]);
        const float4 F1 = step_row(M[1], M[2], M[3], lwI[2], rxI[2]);

        // Critical store: r channel of frame 2k+1 (= u_{2k+2}), read by
        // neighbors next iteration.
        float4* fB = (float4*)(fr + 3 * HW);   // frame 2k+1
        fB[i0] = F0;
        fB[i1] = F1;

        // Publish (bar also protects eX/eW for reuse next iteration).
        __syncthreads();
        if (c4 == 0) st_rel(flag_self, k + 1);

        // Off-chain output (never read): frame 2k full rgb, frame 2k+1 g,b.
        float4* fA = (float4*)fr;              // frame 2k
        __stcs(&fA[i0], M[1]);
        __stcs(&fA[i1], M[2]);
        emit_gb(fA, i0, M[1]);
        emit_gb(fA, i1, M[2]);
        emit_gb(fB, i0, F0);
        emit_gb(fB, i1, F1);

        u0 = F0;
        u1 = F1;
        src = fr + 3 * HW;     // r of frame 2k+1 == u_{2k+2}
        fr += 6 * HW;
    }
}

extern "C" void kernel_launch(void* const* d_in, const int* in_sizes, int n_in,
                              void* d_out, int out_size) {
    const float* init = (const float*)d_in[0];
    float* out = (float*)d_out;
    const int n_frames = out_size / (3 * HW);

    reset_flags_kernel<<<NB / 256, 256>>>();
    physics_persistent_kernel<<<NB, 256>>>(init, out, n_frames);
}